// round 1
// baseline (speedup 1.0000x reference)
#include <cuda_runtime.h>

// GatheringLoss: T=65536 rows (q from trend_representation, r from representation),
// M=1024 keys/values, C=128.
//   score = q @ keys^T ; idx = argmax_row(score)   (first-max tie break, like jnp.argmax)
//   kg[row] = sum_c (q[row,c]-keys[idx,c])^2
//   vg[row] = sum_c (r[row,c]-values[idx,c])^2
// out = [kg (65536) | vg (65536)]

#define T_TOTAL 65536
#define M_KEYS  1024
#define C_DIM   128
#define BM      128
#define BN      128
#define STRIDE  132           // padded row length for [k][m] smem tiles (float4-aligned)
#define THREADS 256

__global__ __launch_bounds__(THREADS, 1)
void gathering_loss_kernel(const float* __restrict__ q,
                           const float* __restrict__ r,
                           const float* __restrict__ keys,
                           const float* __restrict__ values,
                           float* __restrict__ out)
{
    extern __shared__ float smem[];
    float* As = smem;                    // [C_DIM][STRIDE]  As[k*STRIDE + m] = q[row0+m][k]
    float* Bs = smem + C_DIM * STRIDE;   // [C_DIM][STRIDE]  Bs[k*STRIDE + n] = keys[keyTile+n][k]

    const int tid  = threadIdx.x;
    const int row0 = blockIdx.x * BM;
    const int tx   = tid & 15;           // key-tile coordinate
    const int ty   = tid >> 4;           // row-tile coordinate

    // ---- load q tile, transposed into [k][m] (coalesced global reads) ----
    #pragma unroll
    for (int i = 0; i < (BM * C_DIM) / THREADS; ++i) {
        int idx = tid + i * THREADS;
        int k = idx & (C_DIM - 1);
        int m = idx >> 7;
        As[k * STRIDE + m] = q[(row0 + m) * C_DIM + k];
    }

    float best[8];
    int   bidx[8];
    #pragma unroll
    for (int j = 0; j < 8; ++j) { best[j] = -3.402823466e38f; bidx[j] = 0; }

    // ---- key tiles ----
    for (int t = 0; t < M_KEYS / BN; ++t) {
        __syncthreads();  // previous compute done before Bs overwrite (also covers As load on t==0)
        #pragma unroll
        for (int i = 0; i < (BN * C_DIM) / THREADS; ++i) {
            int idx = tid + i * THREADS;
            int k = idx & (C_DIM - 1);
            int n = idx >> 7;
            Bs[k * STRIDE + n] = keys[(t * BN + n) * C_DIM + k];
        }
        __syncthreads();

        float acc[8][8];
        #pragma unroll
        for (int j = 0; j < 8; ++j)
            #pragma unroll
            for (int n = 0; n < 8; ++n) acc[j][n] = 0.f;

        #pragma unroll 4
        for (int k = 0; k < C_DIM; ++k) {
            float4 a0 = *(const float4*)&As[k * STRIDE + ty * 8];
            float4 a1 = *(const float4*)&As[k * STRIDE + ty * 8 + 4];
            float4 b0 = *(const float4*)&Bs[k * STRIDE + tx * 8];
            float4 b1 = *(const float4*)&Bs[k * STRIDE + tx * 8 + 4];
            float av[8] = {a0.x, a0.y, a0.z, a0.w, a1.x, a1.y, a1.z, a1.w};
            float bv[8] = {b0.x, b0.y, b0.z, b0.w, b1.x, b1.y, b1.z, b1.w};
            #pragma unroll
            for (int j = 0; j < 8; ++j)
                #pragma unroll
                for (int n = 0; n < 8; ++n)
                    acc[j][n] = fmaf(av[j], bv[n], acc[j][n]);
        }

        // running argmax; ascending key order + strict '>' keeps the FIRST max
        #pragma unroll
        for (int j = 0; j < 8; ++j)
            #pragma unroll
            for (int n = 0; n < 8; ++n) {
                if (acc[j][n] > best[j]) {
                    best[j] = acc[j][n];
                    bidx[j] = t * BN + tx * 8 + n;
                }
            }
    }
    __syncthreads();  // all compute done before smem reuse

    // ---- reduce argmax across the 16 tx lanes (within each warp half) ----
    #pragma unroll
    for (int off = 8; off >= 1; off >>= 1) {
        #pragma unroll
        for (int j = 0; j < 8; ++j) {
            float ob = __shfl_xor_sync(0xffffffffu, best[j], off);
            int   oi = __shfl_xor_sync(0xffffffffu, bidx[j], off);
            if (ob > best[j] || (ob == best[j] && oi < bidx[j])) {
                best[j] = ob;
                bidx[j] = oi;
            }
        }
    }

    int* sIdx = (int*)smem;  // reuse As region
    if (tx == 0) {
        #pragma unroll
        for (int j = 0; j < 8; ++j) sIdx[ty * 8 + j] = bidx[j];
    }
    __syncthreads();

    // ---- loss epilogue: 2 threads per row, 64 elems each, shfl-combine ----
    {
        int row  = tid >> 1;
        int half = tid & 1;
        int grow = row0 + row;
        int kidx = sIdx[row];
        const float4* qp = (const float4*)(q      + grow * C_DIM + half * 64);
        const float4* kp = (const float4*)(keys   + kidx * C_DIM + half * 64);
        const float4* rp = (const float4*)(r      + grow * C_DIM + half * 64);
        const float4* vp = (const float4*)(values + kidx * C_DIM + half * 64);
        float sk = 0.f, sv = 0.f;
        #pragma unroll
        for (int c = 0; c < 16; ++c) {
            float4 a = qp[c], b = kp[c];
            float d;
            d = a.x - b.x; sk = fmaf(d, d, sk);
            d = a.y - b.y; sk = fmaf(d, d, sk);
            d = a.z - b.z; sk = fmaf(d, d, sk);
            d = a.w - b.w; sk = fmaf(d, d, sk);
            float4 e = rp[c], f = vp[c];
            d = e.x - f.x; sv = fmaf(d, d, sv);
            d = e.y - f.y; sv = fmaf(d, d, sv);
            d = e.z - f.z; sv = fmaf(d, d, sv);
            d = e.w - f.w; sv = fmaf(d, d, sv);
        }
        sk += __shfl_xor_sync(0xffffffffu, sk, 1);
        sv += __shfl_xor_sync(0xffffffffu, sv, 1);
        if (half == 0) out[grow]           = sk;
        else           out[T_TOTAL + grow] = sv;
    }
}

extern "C" void kernel_launch(void* const* d_in, const int* in_sizes, int n_in,
                              void* d_out, int out_size)
{
    const float* q      = (const float*)d_in[0];  // trend_representation (32,2048,128)
    const float* r      = (const float*)d_in[1];  // representation      (32,2048,128)
    const float* keys   = (const float*)d_in[2];  // (1024,128)
    const float* values = (const float*)d_in[3];  // (1024,128)
    float* out = (float*)d_out;

    const int smem_bytes = 2 * C_DIM * STRIDE * (int)sizeof(float);  // 135168
    cudaFuncSetAttribute(gathering_loss_kernel,
                         cudaFuncAttributeMaxDynamicSharedMemorySize, smem_bytes);

    gathering_loss_kernel<<<T_TOTAL / BM, THREADS, smem_bytes>>>(q, r, keys, values, out);
}